// round 9
// baseline (speedup 1.0000x reference)
#include <cuda_runtime.h>
#include <cstdint>

#define BATCH 256
#define NSRC  10
#define NMC_C 16
#define LL_C  128
#define PLANE (LL_C * LL_C)

// ---------------------------------------------------------------------------
// Fill (identical to the proven 70us / 7.66TB/s version): one float4 store
// per thread, grid covers output exactly. Channel of float4 i = (i>>12)&31.
// Trigger fires PDL launch of the scatter kernel as blocks start.
// ---------------------------------------------------------------------------
__global__ void __launch_bounds__(256) fill_kernel(float4* __restrict__ out) {
    cudaTriggerProgrammaticLaunchCompletion();
    long i = (long)blockIdx.x * blockDim.x + threadIdx.x;
    float v = (((i >> 12) & 31) < NMC_C) ? 1.0f : 0.0f;
    out[i] = make_float4(v, v, v, v);
}

// ---------------------------------------------------------------------------
// Scatter with PDL: long-latency preamble (coord loads + log10 + index math)
// runs concurrently with the fill kernel's tail; only the two tiny stores
// happen after cudaGridDependencySynchronize().
// ---------------------------------------------------------------------------
__global__ void __launch_bounds__(256) scatter_kernel(
    const float* __restrict__ coord,
    const float* __restrict__ lows,
    const float* __restrict__ highs,
    float* __restrict__ out)
{
    int t = blockIdx.x * blockDim.x + threadIdx.x;
    bool active = (t < BATCH * NSRC);

    size_t off0 = 0, off1 = 0;
    if (active) {
        int b = t / NSRC;
        int s = t - b * NSRC;

        const float* c = coord + (size_t)b * (3 * NSRC) + s * 3;
        float x = c[0], y = c[1], m = c[2];
        float lo0 = lows[0], lo1 = lows[1], lo2 = lows[2];
        float hi0 = highs[0], hi1 = highs[1], hi2 = highs[2];

        float xg = (x          - lo0) / (hi0 - lo0);
        float yg = (y          - lo1) / (hi1 - lo1);
        float mg = (log10f(m)  - lo2) / (hi2 - lo2);

        int xi = (int)floorf(xg * (float)LL_C);
        int yi = (int)floorf(yg * (float)LL_C);
        int mi = (int)floorf(mg * (float)NMC_C);

        if ((unsigned)xi >= LL_C || (unsigned)yi >= LL_C || (unsigned)mi >= NMC_C) {
            active = false;   // drop OOB like JAX scatter
        } else {
            size_t base = (size_t)b * (2 * NMC_C) * PLANE + (size_t)yi * LL_C + xi;
            off0 = base + (size_t)mi * PLANE;             // (1 - z) half -> 0
            off1 = base + (size_t)(NMC_C + mi) * PLANE;   // z half       -> 1
        }
    }

    // Wait for fill to fully complete (all its stores visible), then patch.
    cudaGridDependencySynchronize();

    if (active) {
        out[off0] = 0.0f;
        out[off1] = 1.0f;
    }
}

extern "C" void kernel_launch(void* const* d_in, const int* in_sizes, int n_in,
                              void* d_out, int out_size) {
    const float* coord = (const float*)d_in[0];
    const float* lows  = (const float*)d_in[1];
    const float* highs = (const float*)d_in[2];
    float* out = (float*)d_out;

    long n4 = (long)out_size / 4;          // 33,554,432 float4
    long blocks = n4 / 256;                // 131072, exact
    fill_kernel<<<(unsigned)blocks, 256>>>((float4*)out);

    // Scatter launched with programmatic stream serialization (PDL):
    // it may begin executing while fill is still running; the grid-dependency
    // sync inside orders its stores after fill's completion.
    cudaLaunchConfig_t cfg = {};
    int npts = BATCH * NSRC;
    cfg.gridDim  = dim3((npts + 255) / 256);
    cfg.blockDim = dim3(256);
    cfg.dynamicSmemBytes = 0;
    cfg.stream = 0;

    cudaLaunchAttribute attrs[1];
    attrs[0].id = cudaLaunchAttributeProgrammaticStreamSerialization;
    attrs[0].val.programmaticStreamSerializationAllowed = 1;
    cfg.attrs = attrs;
    cfg.numAttrs = 1;

    cudaLaunchKernelEx(&cfg, scatter_kernel, coord, lows, highs, out);
}

// round 10
// speedup vs baseline: 1.6182x; 1.6182x over previous
#include <cuda_runtime.h>
#include <cstdint>

#define BATCH 256
#define NSRC  10
#define NMC_C 16
#define LL_C  128
#define PLANE (LL_C * LL_C)            // 16384 floats per channel plane

#define TPB      256
#define NFILL    131072                // fill blocks: 131072 * 256 float4 = whole output
#define NCTR     32                    // arrival counters (spread over LTS slices)
#define CTR_STRIDE 64                  // 64 uints = 256B apart
#define CTR_TARGET (NFILL / NCTR)      // 4096 arrivals per counter

// Zero-initialized at module load; each launch returns it to all-zeros.
__device__ unsigned g_ctr[NCTR * CTR_STRIDE];

__global__ void __launch_bounds__(TPB) fused_kernel(
    const float* __restrict__ coord,
    const float* __restrict__ lows,
    const float* __restrict__ highs,
    float* __restrict__ out)
{
    int bid = blockIdx.x;
    int t   = threadIdx.x;

    if (bid < NFILL) {
        // ---- proven roofline fill: one STG.128 per thread ----
        long i = (long)bid * TPB + t;
        float v = (((i >> 12) & 31) < NMC_C) ? 1.0f : 0.0f;
        ((float4*)out)[i] = make_float4(v, v, v, v);

        // publish completion: stores -> bar -> fence -> RED (fire-and-forget)
        __syncthreads();
        if (t == 0) {
            __threadfence();
            atomicAdd(&g_ctr[(bid & (NCTR - 1)) * CTR_STRIDE], 1u);  // result unused -> REDG
        }
    } else {
        // ---- single scatter block (last wave): overlap preamble with fill ----
        int offs[NSRC];
        unsigned valid = 0;

        float lo0 = lows[0], lo1 = lows[1], lo2 = lows[2];
        float hi0 = highs[0], hi1 = highs[1], hi2 = highs[2];

#pragma unroll
        for (int k = 0; k < NSRC; k++) {
            int pt = t + k * TPB;            // 0..2559
            int b  = pt / NSRC;
            int s  = pt - b * NSRC;
            const float* c = coord + (size_t)b * (3 * NSRC) + s * 3;

            float xg = (c[0]         - lo0) / (hi0 - lo0);
            float yg = (c[1]         - lo1) / (hi1 - lo1);
            float mg = (log10f(c[2]) - lo2) / (hi2 - lo2);

            int xi = (int)floorf(xg * (float)LL_C);
            int yi = (int)floorf(yg * (float)LL_C);
            int mi = (int)floorf(mg * (float)NMC_C);

            bool ok = ((unsigned)xi < LL_C) & ((unsigned)yi < LL_C) &
                      ((unsigned)mi < NMC_C);
            offs[k] = b * (2 * NMC_C * PLANE) + mi * PLANE + yi * LL_C + xi;
            valid |= (ok ? 1u : 0u) << k;
        }

        // spin until all fill blocks have arrived (acquire pairs with REDs)
        if (t < NCTR) {
            unsigned* p = &g_ctr[t * CTR_STRIDE];
            unsigned v;
            for (;;) {
                asm volatile("ld.acquire.gpu.global.u32 %0, [%1];"
                             : "=r"(v) : "l"(p) : "memory");
                if (v >= CTR_TARGET) break;
                __nanosleep(100);
            }
        }
        __syncthreads();

        // apply the 2*2560 overrides
#pragma unroll
        for (int k = 0; k < NSRC; k++) {
            if (valid & (1u << k)) {
                out[offs[k]]                 = 0.0f;   // (1 - z) half
                out[offs[k] + NMC_C * PLANE] = 1.0f;   // z half
            }
        }

        // reset counters for the next graph replay (stream-ordered vs next launch)
        __syncthreads();
        if (t < NCTR) g_ctr[t * CTR_STRIDE] = 0u;
    }
}

extern "C" void kernel_launch(void* const* d_in, const int* in_sizes, int n_in,
                              void* d_out, int out_size) {
    const float* coord = (const float*)d_in[0];
    const float* lows  = (const float*)d_in[1];
    const float* highs = (const float*)d_in[2];
    float* out = (float*)d_out;

    fused_kernel<<<NFILL + 1, TPB>>>(coord, lows, highs, out);
}